// round 14
// baseline (speedup 1.0000x reference)
#include <cuda_runtime.h>
#include <cuda_fp16.h>
#include <cstdint>

// Complex attention, fp16 m16n8k16 mma.sync. R13 skeleton with smem padding
// replaced by XOR swizzle (ROWB 176->128): 64KB/CTA -> 3 CTAs/SM for deeper
// cross-CTA latency hiding.

#define S_LEN   2048
#define DH      64
#define BH      32
#define QT      64
#define NT      64
#define NTILES  (S_LEN / NT)
#define THREADS 128
#define NITEMS  1024            // 32 q-tiles x 32 heads
#define GRID    456             // 3 CTAs per SM (152 SMs)
#define ROWB    128             // swizzled, no padding
#define PL_STR  (NT * ROWB)     // 8192

#define KP(buf, pl) (((buf) * 2 + (pl)) * PL_STR)
#define V_B     (4 * PL_STR)
#define VP(buf, pl) (V_B + ((buf) * 2 + (pl)) * PL_STR)
#define SMEM_BYTES (8 * PL_STR) // 65536

#define ELEMS (BH * S_LEN * DH)

__device__ __align__(16) __half gQr[ELEMS];
__device__ __align__(16) __half gQi[ELEMS];
__device__ __align__(16) __half gKr[ELEMS];
__device__ __align__(16) __half gKi[ELEMS];
__device__ __align__(16) __half gVtr[ELEMS];   // [bh][d][s]
__device__ __align__(16) __half gVti[ELEMS];

__device__ unsigned int g_ticket;
__global__ void reset_ticket_kernel() { g_ticket = 0u; }

// ---- prep: elementwise fp32 -> fp16 (Q scaled by 1/8) ----
__global__ void conv_kernel(const float* __restrict__ q_r, const float* __restrict__ q_i,
                            const float* __restrict__ k_r, const float* __restrict__ k_i)
{
    const int ts = blockIdx.y;
    const float* src = (ts == 0) ? q_r : (ts == 1) ? q_i : (ts == 2) ? k_r : k_i;
    __half* dst = (ts == 0) ? gQr : (ts == 1) ? gQi : (ts == 2) ? gKr : gKi;
    const float sc = (ts < 2) ? 0.125f : 1.0f;
    const int n4 = ELEMS / 4;
    for (int i = blockIdx.x * blockDim.x + threadIdx.x; i < n4; i += gridDim.x * blockDim.x) {
        float4 v = ((const float4*)src)[i];
        __half2* d2 = (__half2*)(dst + (size_t)i * 4);
        d2[0] = __floats2half2_rn(v.x * sc, v.y * sc);
        d2[1] = __floats2half2_rn(v.z * sc, v.w * sc);
    }
}

// ---- prep: V [s][d] fp32 -> Vt [d][s] fp16 (tiled transpose) ----
__global__ void prep_vt_kernel(const float* __restrict__ v_r, const float* __restrict__ v_i)
{
    __shared__ float tr[32][33], ti[32][33];
    const int s0 = blockIdx.x * 32, d0 = blockIdx.y * 32, bh = blockIdx.z;
    const int tx = threadIdx.x, ty = threadIdx.y;
    const long long ib = (long long)bh * S_LEN * DH;
    #pragma unroll
    for (int k = 0; k < 4; ++k) {
        int r = ty + k * 8;
        tr[r][tx] = v_r[ib + (long long)(s0 + r) * DH + d0 + tx];
        ti[r][tx] = v_i[ib + (long long)(s0 + r) * DH + d0 + tx];
    }
    __syncthreads();
    const long long ob = (long long)bh * DH * S_LEN;
    #pragma unroll
    for (int k = 0; k < 4; ++k) {
        int r = ty + k * 8;
        gVtr[ob + (long long)(d0 + r) * S_LEN + s0 + tx] = __float2half_rn(tr[tx][r]);
        gVti[ob + (long long)(d0 + r) * S_LEN + s0 + tx] = __float2half_rn(ti[tx][r]);
    }
}

// ---- helpers ----
__device__ __forceinline__ uint32_t cvta_s(const void* p) {
    uint32_t a;
    asm("{ .reg .u64 t; cvta.to.shared.u64 t, %1; cvt.u32.u64 %0, t; }" : "=r"(a) : "l"(p));
    return a;
}
__device__ __forceinline__ void cpa16(uint32_t dst, const void* src) {
    asm volatile("cp.async.ca.shared.global [%0], [%1], 16;" :: "r"(dst), "l"(src));
}
#define CP_COMMIT() asm volatile("cp.async.commit_group;" ::: "memory")
#define CP_WAIT0()  asm volatile("cp.async.wait_group 0;" ::: "memory")

__device__ __forceinline__ uint32_t pkh(float lo, float hi) {
    uint32_t d; asm("cvt.rn.f16x2.f32 %0, %1, %2;" : "=r"(d) : "f"(hi), "f"(lo)); return d;
}
__device__ __forceinline__ uint4 ldsm4(uint32_t a) {
    uint4 r;
    asm volatile("ldmatrix.sync.aligned.m8n8.x4.shared.b16 {%0,%1,%2,%3}, [%4];"
        : "=r"(r.x), "=r"(r.y), "=r"(r.z), "=r"(r.w) : "r"(a));
    return r;
}
__device__ __forceinline__ void mma16(float* d, const uint32_t* a, uint32_t b0, uint32_t b1) {
    asm volatile(
        "mma.sync.aligned.m16n8k16.row.col.f32.f16.f16.f32 "
        "{%0,%1,%2,%3}, {%4,%5,%6,%7}, {%8,%9}, {%0,%1,%2,%3};"
        : "+f"(d[0]), "+f"(d[1]), "+f"(d[2]), "+f"(d[3])
        : "r"(a[0]), "r"(a[1]), "r"(a[2]), "r"(a[3]), "r"(b0), "r"(b1));
}

__global__ __launch_bounds__(THREADS, 3)
void cv_attn_h8_kernel(float* __restrict__ out, long long plane)
{
    extern __shared__ char sm[];
    __shared__ int s_item;
    const uint32_t smb = cvta_s(sm);

    const int tid  = threadIdx.x;
    const int w    = tid >> 5;
    const int lane = tid & 31;
    const int g4   = lane >> 2;
    const int j4   = lane & 3;
    const int r0   = w * 16 + g4;      // rows 0..63

    // ldmatrix lane decomposition: r = row-in-8, hb = k-high chunk, plane bit
    const int lr   = lane & 7;
    const int lhb  = (lane >> 3) & 1;
    const uint32_t laneBase = (uint32_t)(lr * ROWB) + ((lane & 16) ? (uint32_t)PL_STR : 0u);

    for (;;) {
        if (tid == 0) s_item = (int)atomicAdd(&g_ticket, 1u);
        __syncthreads();
        const int item = s_item;
        if (item >= NITEMS) break;

        const int bh  = item >> 5;
        const int s0t = (item & 31) * QT;
        const long long bbH = (long long)bh * S_LEN * DH;

        auto copy_tile = [&](int t, int buf) {
            #pragma unroll
            for (int it = 0; it < 16; ++it) {
                const int i = tid + it * THREADS;    // 2048 x 16B chunks
                const int tensor = i >> 10;          // 0:K 1:Vt
                const int pl  = (i >> 9) & 1;
                const int row = (i >> 3) & 63;
                const int c16 = i & 7;
                const int sc16 = c16 ^ (row & 7);    // XOR swizzle
                const __half* src;
                uint32_t dst;
                if (tensor == 0) {
                    src = (pl ? gKi : gKr) + bbH + (long long)(t * NT + row) * DH + c16 * 8;
                    dst = smb + (uint32_t)KP(buf, pl) + (uint32_t)(row * ROWB + sc16 * 16);
                } else {
                    src = (pl ? gVti : gVtr) + bbH + (long long)row * S_LEN + t * NT + c16 * 8;
                    dst = smb + (uint32_t)VP(buf, pl) + (uint32_t)(row * ROWB + sc16 * 16);
                }
                cpa16(dst, src);
            }
            CP_COMMIT();
        };

        // ---- Q fragments -> registers (fp16 gmem, already scaled) ----
        uint32_t qfr[4][4], qfi[4][4];
        {
            const long long b0 = bbH + (long long)(s0t + r0) * DH;
            const long long b8 = bbH + (long long)(s0t + r0 + 8) * DH;
            #pragma unroll
            for (int ks = 0; ks < 4; ++ks) {
                const int c = ks * 16 + 2 * j4;
                qfr[ks][0] = *(const uint32_t*)(gQr + b0 + c);
                qfr[ks][1] = *(const uint32_t*)(gQr + b8 + c);
                qfr[ks][2] = *(const uint32_t*)(gQr + b0 + c + 8);
                qfr[ks][3] = *(const uint32_t*)(gQr + b8 + c + 8);
                qfi[ks][0] = *(const uint32_t*)(gQi + b0 + c);
                qfi[ks][1] = *(const uint32_t*)(gQi + b8 + c);
                qfi[ks][2] = *(const uint32_t*)(gQi + b0 + c + 8);
                qfi[ks][3] = *(const uint32_t*)(gQi + b8 + c + 8);
            }
        }

        copy_tile(0, 0);

        float ore[8][4], oim[8][4];
        #pragma unroll
        for (int nb = 0; nb < 8; ++nb)
            #pragma unroll
            for (int c = 0; c < 4; ++c) { ore[nb][c] = 0.f; oim[nb][c] = 0.f; }
        float l0 = 0.f, l1 = 0.f;

        for (int t = 0; t < NTILES; ++t) {
            const int cur = t & 1;
            CP_WAIT0();
            __syncthreads();
            if (t + 1 < NTILES) copy_tile(t + 1, cur ^ 1);

            const uint32_t kbase = smb + (uint32_t)KP(cur, 0) + laneBase;
            const uint32_t vbase = smb + (uint32_t)VP(cur, 0) + laneBase;

            // ---- fused pipeline over nb-pairs p ----
            #pragma unroll
            for (int p = 0; p < 4; ++p) {
                float sre[2][4], sim[2][4];
                #pragma unroll
                for (int b = 0; b < 2; ++b)
                    #pragma unroll
                    for (int c = 0; c < 4; ++c) { sre[b][c] = 0.f; sim[b][c] = 0.f; }

                #pragma unroll
                for (int ks = 0; ks < 4; ++ks) {
                    const uint32_t swz = (uint32_t)(((2 * ks + lhb) ^ lr) << 4);
                    #pragma unroll
                    for (int b = 0; b < 2; ++b) {
                        uint4 f = ldsm4(kbase + (2 * p + b) * (8 * ROWB) + swz);
                        uint32_t nqb[4];
                        #pragma unroll
                        for (int k = 0; k < 4; ++k) nqb[k] = qfi[ks][k] ^ 0x80008000u;
                        mma16(sre[b], qfr[ks], f.x, f.y);
                        mma16(sre[b], nqb,     f.z, f.w);
                        mma16(sim[b], qfr[ks], f.z, f.w);
                        mma16(sim[b], qfi[ks], f.x, f.y);
                    }
                }

                #pragma unroll
                for (int b = 0; b < 2; ++b) {
                    #pragma unroll
                    for (int c = 0; c < 4; ++c) {
                        float re = sre[b][c], im = sim[b][c];
                        float m2  = fmaxf(fmaf(re, re, im * im), 1e-24f);
                        float inv = rsqrtf(m2);
                        float mag = m2 * inv;
                        float e   = __expf(mag);
                        if (c < 2) l0 += e; else l1 += e;
                        float pw = e * inv;
                        sre[b][c] = re * pw;
                        sim[b][c] = im * pw;
                    }
                }

                uint32_t pa[4], pb[4], npb[4];
                pa[0] = pkh(sre[0][0], sre[0][1]);
                pa[1] = pkh(sre[0][2], sre[0][3]);
                pa[2] = pkh(sre[1][0], sre[1][1]);
                pa[3] = pkh(sre[1][2], sre[1][3]);
                pb[0] = pkh(sim[0][0], sim[0][1]);
                pb[1] = pkh(sim[0][2], sim[0][3]);
                pb[2] = pkh(sim[1][0], sim[1][1]);
                pb[3] = pkh(sim[1][2], sim[1][3]);
                #pragma unroll
                for (int k = 0; k < 4; ++k) npb[k] = pb[k] ^ 0x80008000u;

                // GEMM2 slice ks = p
                const uint32_t vswz = (uint32_t)(((2 * p + lhb) ^ lr) << 4);
                #pragma unroll
                for (int nb = 0; nb < 8; ++nb) {
                    uint4 f = ldsm4(vbase + nb * (8 * ROWB) + vswz);
                    mma16(ore[nb], pa,  f.x, f.y);
                    mma16(ore[nb], npb, f.z, f.w);
                    mma16(oim[nb], pa,  f.z, f.w);
                    mma16(oim[nb], pb,  f.x, f.y);
                }
            }
        }

        __syncthreads();   // all smem tile reads done; reuse as output stage

        l0 += __shfl_xor_sync(~0u, l0, 1); l0 += __shfl_xor_sync(~0u, l0, 2);
        l1 += __shfl_xor_sync(~0u, l1, 1); l1 += __shfl_xor_sync(~0u, l1, 2);
        const float il0 = 1.0f / l0, il1 = 1.0f / l1;

        float* stg = (float*)sm;            // [64][132]: 0..63 re, 64..127 im
        #pragma unroll
        for (int nb = 0; nb < 8; ++nb) {
            const int d0 = nb * 8 + 2 * j4;
            stg[ r0      * 132 + d0    ]      = ore[nb][0] * il0;
            stg[ r0      * 132 + d0 + 1]      = ore[nb][1] * il0;
            stg[(r0 + 8) * 132 + d0    ]      = ore[nb][2] * il1;
            stg[(r0 + 8) * 132 + d0 + 1]      = ore[nb][3] * il1;
            stg[ r0      * 132 + 64 + d0]     = oim[nb][0] * il0;
            stg[ r0      * 132 + 64 + d0 + 1] = oim[nb][1] * il0;
            stg[(r0 + 8) * 132 + 64 + d0]     = oim[nb][2] * il1;
            stg[(r0 + 8) * 132 + 64 + d0 + 1] = oim[nb][3] * il1;
        }
        __syncthreads();

        for (int i = tid; i < QT * 32; i += THREADS) {
            const int row = i >> 5, c = i & 31;
            float4 v = *(const float4*)(stg + row * 132 + c * 4);
            if (c < 16)
                *(float4*)(out + bbH + (long long)(s0t + row) * DH + c * 4) = v;
            else
                *(float4*)(out + plane + bbH + (long long)(s0t + row) * DH + (c - 16) * 4) = v;
        }
        __syncthreads();   // stage consumed before next item's tile copies land
    }
}

extern "C" void kernel_launch(void* const* d_in, const int* in_sizes, int n_in,
                              void* d_out, int out_size) {
    const float* qr = (const float*)d_in[0];
    const float* qi = (const float*)d_in[1];
    const float* kr = (const float*)d_in[2];
    const float* ki = (const float*)d_in[3];
    const float* vr = (const float*)d_in[4];
    const float* vi = (const float*)d_in[5];

    const long long plane = (long long)in_sizes[0];   // B*H*S*D

    static int configured = 0;
    if (!configured) {
        cudaFuncSetAttribute(cv_attn_h8_kernel,
                             cudaFuncAttributeMaxDynamicSharedMemorySize, SMEM_BYTES);
        configured = 1;
    }

    reset_ticket_kernel<<<1, 1>>>();
    {
        dim3 g(1024, 4);
        conv_kernel<<<g, 256>>>(qr, qi, kr, ki);
    }
    {
        dim3 g(S_LEN / 32, DH / 32, BH);
        prep_vt_kernel<<<g, dim3(32, 8)>>>(vr, vi);
    }
    cv_attn_h8_kernel<<<GRID, THREADS, SMEM_BYTES>>>((float*)d_out, plane);
}

// round 15
// speedup vs baseline: 1.0883x; 1.0883x over previous
#include <cuda_runtime.h>
#include <cuda_fp16.h>
#include <cstdint>

// Complex attention, fp16 m16n8k16 mma.sync. R13 compute skeleton (best) +
// XOR-swizzled smem (validated R14), 3-stage cp.async pipeline (wait_group 1),
// and all prep (ticket reset, Q/K->fp16 convert, V transpose) fused into ONE
// launch. 2 CTAs/SM @ 255 regs (measured optimum).

#define S_LEN   2048
#define DH      64
#define BH      32
#define QT      64
#define NT      64
#define NTILES  (S_LEN / NT)
#define THREADS 128
#define NITEMS  1024            // 32 q-tiles x 32 heads
#define GRID    304             // 2 CTAs per SM
#define ROWB    128             // swizzled rows, no padding
#define PL_STR  (NT * ROWB)     // 8192 (plane stride inside a buffer)
#define BUF_STR (4 * PL_STR)    // 32768 (K re/im + V re/im)

#define KP(buf, pl) ((buf) * BUF_STR + (pl) * PL_STR)
#define VP(buf, pl) ((buf) * BUF_STR + 2 * PL_STR + (pl) * PL_STR)
#define SMEM_BYTES (3 * BUF_STR)    // 98304

#define ELEMS (BH * S_LEN * DH)

__device__ __align__(16) __half gQr[ELEMS];
__device__ __align__(16) __half gQi[ELEMS];
__device__ __align__(16) __half gKr[ELEMS];
__device__ __align__(16) __half gKi[ELEMS];
__device__ __align__(16) __half gVtr[ELEMS];   // [bh][d][s]
__device__ __align__(16) __half gVti[ELEMS];

__device__ unsigned int g_ticket;

// ---- fused prep: ticket reset + Q/K fp32->fp16 (Q x 1/8) + V transpose ----
// grid (64, 2, 32), block (32, 8)
__global__ void prep_kernel(const float* __restrict__ q_r, const float* __restrict__ q_i,
                            const float* __restrict__ k_r, const float* __restrict__ k_i,
                            const float* __restrict__ v_r, const float* __restrict__ v_i)
{
    const int tx = threadIdx.x, ty = threadIdx.y;
    const int b  = blockIdx.x + 64 * (blockIdx.y + 2 * blockIdx.z);
    if (b == 0 && tx == 0 && ty == 0) g_ticket = 0u;

    // conv part: 4096 blocks x 1024 float4 = 4 tensors x 1048576 float4
    {
        const int t = ty * 32 + tx;
        #pragma unroll
        for (int i = 0; i < 4; ++i) {
            const int idx = b * 1024 + t + i * 256;
            const int ts  = idx >> 20;
            const int off = idx & 0xFFFFF;
            const float4* src = (ts == 0) ? (const float4*)q_r :
                                (ts == 1) ? (const float4*)q_i :
                                (ts == 2) ? (const float4*)k_r : (const float4*)k_i;
            __half* dst = (ts == 0) ? gQr : (ts == 1) ? gQi : (ts == 2) ? gKr : gKi;
            const float sc = (ts < 2) ? 0.125f : 1.0f;
            float4 v = src[off];
            __half2* d2 = (__half2*)(dst + (size_t)off * 4);
            d2[0] = __floats2half2_rn(v.x * sc, v.y * sc);
            d2[1] = __floats2half2_rn(v.z * sc, v.w * sc);
        }
    }

    // vt part: 32x32 tiled transpose (identical math to previous prep_vt)
    __shared__ float tr[32][33], ti[32][33];
    const int s0 = blockIdx.x * 32, d0 = blockIdx.y * 32, bh = blockIdx.z;
    const long long ib = (long long)bh * S_LEN * DH;
    #pragma unroll
    for (int k = 0; k < 4; ++k) {
        int r = ty + k * 8;
        tr[r][tx] = v_r[ib + (long long)(s0 + r) * DH + d0 + tx];
        ti[r][tx] = v_i[ib + (long long)(s0 + r) * DH + d0 + tx];
    }
    __syncthreads();
    const long long ob = (long long)bh * DH * S_LEN;
    #pragma unroll
    for (int k = 0; k < 4; ++k) {
        int r = ty + k * 8;
        gVtr[ob + (long long)(d0 + r) * S_LEN + s0 + tx] = __float2half_rn(tr[tx][r]);
        gVti[ob + (long long)(d0 + r) * S_LEN + s0 + tx] = __float2half_rn(ti[tx][r]);
    }
}

// ---- helpers ----
__device__ __forceinline__ uint32_t cvta_s(const void* p) {
    uint32_t a;
    asm("{ .reg .u64 t; cvta.to.shared.u64 t, %1; cvt.u32.u64 %0, t; }" : "=r"(a) : "l"(p));
    return a;
}
__device__ __forceinline__ void cpa16(uint32_t dst, const void* src) {
    asm volatile("cp.async.ca.shared.global [%0], [%1], 16;" :: "r"(dst), "l"(src));
}
#define CP_COMMIT() asm volatile("cp.async.commit_group;" ::: "memory")
#define CP_WAIT0()  asm volatile("cp.async.wait_group 0;" ::: "memory")
#define CP_WAIT1()  asm volatile("cp.async.wait_group 1;" ::: "memory")

__device__ __forceinline__ uint32_t pkh(float lo, float hi) {
    uint32_t d; asm("cvt.rn.f16x2.f32 %0, %1, %2;" : "=r"(d) : "f"(hi), "f"(lo)); return d;
}
__device__ __forceinline__ uint4 ldsm4(uint32_t a) {
    uint4 r;
    asm volatile("ldmatrix.sync.aligned.m8n8.x4.shared.b16 {%0,%1,%2,%3}, [%4];"
        : "=r"(r.x), "=r"(r.y), "=r"(r.z), "=r"(r.w) : "r"(a));
    return r;
}
__device__ __forceinline__ void mma16(float* d, const uint32_t* a, uint32_t b0, uint32_t b1) {
    asm volatile(
        "mma.sync.aligned.m16n8k16.row.col.f32.f16.f16.f32 "
        "{%0,%1,%2,%3}, {%4,%5,%6,%7}, {%8,%9}, {%0,%1,%2,%3};"
        : "+f"(d[0]), "+f"(d[1]), "+f"(d[2]), "+f"(d[3])
        : "r"(a[0]), "r"(a[1]), "r"(a[2]), "r"(a[3]), "r"(b0), "r"(b1));
}

__global__ __launch_bounds__(THREADS, 2)
void cv_attn_h9_kernel(float* __restrict__ out, long long plane)
{
    extern __shared__ char sm[];
    __shared__ int s_item;
    const uint32_t smb = cvta_s(sm);

    const int tid  = threadIdx.x;
    const int w    = tid >> 5;
    const int lane = tid & 31;
    const int g4   = lane >> 2;
    const int j4   = lane & 3;
    const int r0   = w * 16 + g4;      // rows 0..63

    // ldmatrix lane decomposition for swizzled layout
    const int lr   = lane & 7;
    const int lhb  = (lane >> 3) & 1;
    const uint32_t laneBase = (uint32_t)(lr * ROWB) + ((lane & 16) ? (uint32_t)PL_STR : 0u);

    for (;;) {
        if (tid == 0) s_item = (int)atomicAdd(&g_ticket, 1u);
        __syncthreads();
        const int item = s_item;
        if (item >= NITEMS) break;

        const int bh  = item >> 5;
        const int s0t = (item & 31) * QT;
        const long long bbH = (long long)bh * S_LEN * DH;

        auto copy_tile = [&](int t, int buf) {
            #pragma unroll
            for (int it = 0; it < 16; ++it) {
                const int i = tid + it * THREADS;    // 2048 x 16B chunks
                const int tensor = i >> 10;          // 0:K 1:Vt
                const int pl  = (i >> 9) & 1;
                const int row = (i >> 3) & 63;
                const int c16 = i & 7;
                const int sc16 = c16 ^ (row & 7);    // XOR swizzle
                const __half* src;
                uint32_t dst;
                if (tensor == 0) {
                    src = (pl ? gKi : gKr) + bbH + (long long)(t * NT + row) * DH + c16 * 8;
                    dst = smb + (uint32_t)KP(buf, pl) + (uint32_t)(row * ROWB + sc16 * 16);
                } else {
                    src = (pl ? gVti : gVtr) + bbH + (long long)row * S_LEN + t * NT + c16 * 8;
                    dst = smb + (uint32_t)VP(buf, pl) + (uint32_t)(row * ROWB + sc16 * 16);
                }
                cpa16(dst, src);
            }
            CP_COMMIT();
        };

        // ---- Q fragments -> registers (fp16 gmem, already scaled); nqb hoisted ----
        uint32_t qfr[4][4], qfi[4][4], nqb[4][4];
        {
            const long long b0 = bbH + (long long)(s0t + r0) * DH;
            const long long b8 = bbH + (long long)(s0t + r0 + 8) * DH;
            #pragma unroll
            for (int ks = 0; ks < 4; ++ks) {
                const int c = ks * 16 + 2 * j4;
                qfr[ks][0] = *(const uint32_t*)(gQr + b0 + c);
                qfr[ks][1] = *(const uint32_t*)(gQr + b8 + c);
                qfr[ks][2] = *(const uint32_t*)(gQr + b0 + c + 8);
                qfr[ks][3] = *(const uint32_t*)(gQr + b8 + c + 8);
                qfi[ks][0] = *(const uint32_t*)(gQi + b0 + c);
                qfi[ks][1] = *(const uint32_t*)(gQi + b8 + c);
                qfi[ks][2] = *(const uint32_t*)(gQi + b0 + c + 8);
                qfi[ks][3] = *(const uint32_t*)(gQi + b8 + c + 8);
                #pragma unroll
                for (int k = 0; k < 4; ++k) nqb[ks][k] = qfi[ks][k] ^ 0x80008000u;
            }
        }

        copy_tile(0, 0);
        copy_tile(1, 1);

        float ore[8][4], oim[8][4];
        #pragma unroll
        for (int nb = 0; nb < 8; ++nb)
            #pragma unroll
            for (int c = 0; c < 4; ++c) { ore[nb][c] = 0.f; oim[nb][c] = 0.f; }
        float l0 = 0.f, l1 = 0.f;

        for (int t = 0; t < NTILES; ++t) {
            const int cur = t % 3;
            if (t + 1 < NTILES) { CP_WAIT1(); } else { CP_WAIT0(); }
            __syncthreads();
            if (t + 2 < NTILES) copy_tile(t + 2, (t + 2) % 3);

            const uint32_t kbase = smb + (uint32_t)KP(cur, 0) + laneBase;
            const uint32_t vbase = smb + (uint32_t)VP(cur, 0) + laneBase;

            // ---- fused pipeline over nb-pairs p ----
            #pragma unroll
            for (int p = 0; p < 4; ++p) {
                float sre[2][4], sim[2][4];
                #pragma unroll
                for (int b = 0; b < 2; ++b)
                    #pragma unroll
                    for (int c = 0; c < 4; ++c) { sre[b][c] = 0.f; sim[b][c] = 0.f; }

                #pragma unroll
                for (int ks = 0; ks < 4; ++ks) {
                    const uint32_t swz = (uint32_t)(((2 * ks + lhb) ^ lr) << 4);
                    #pragma unroll
                    for (int b = 0; b < 2; ++b) {
                        uint4 f = ldsm4(kbase + (2 * p + b) * (8 * ROWB) + swz);
                        mma16(sre[b], qfr[ks], f.x, f.y);
                        mma16(sre[b], nqb[ks], f.z, f.w);
                        mma16(sim[b], qfr[ks], f.z, f.w);
                        mma16(sim[b], qfi[ks], f.x, f.y);
                    }
                }

                #pragma unroll
                for (int b = 0; b < 2; ++b) {
                    #pragma unroll
                    for (int c = 0; c < 4; ++c) {
                        float re = sre[b][c], im = sim[b][c];
                        float m2  = fmaxf(fmaf(re, re, im * im), 1e-24f);
                        float inv = rsqrtf(m2);
                        float mag = m2 * inv;
                        float e   = __expf(mag);
                        if (c < 2) l0 += e; else l1 += e;
                        float pw = e * inv;
                        sre[b][c] = re * pw;
                        sim[b][c] = im * pw;
                    }
                }

                uint32_t pa[4], pb[4], npb[4];
                pa[0] = pkh(sre[0][0], sre[0][1]);
                pa[1] = pkh(sre[0][2], sre[0][3]);
                pa[2] = pkh(sre[1][0], sre[1][1]);
                pa[3] = pkh(sre[1][2], sre[1][3]);
                pb[0] = pkh(sim[0][0], sim[0][1]);
                pb[1] = pkh(sim[0][2], sim[0][3]);
                pb[2] = pkh(sim[1][0], sim[1][1]);
                pb[3] = pkh(sim[1][2], sim[1][3]);
                #pragma unroll
                for (int k = 0; k < 4; ++k) npb[k] = pb[k] ^ 0x80008000u;

                // GEMM2 slice ks = p
                const uint32_t vswz = (uint32_t)(((2 * p + lhb) ^ lr) << 4);
                #pragma unroll
                for (int nb = 0; nb < 8; ++nb) {
                    uint4 f = ldsm4(vbase + nb * (8 * ROWB) + vswz);
                    mma16(ore[nb], pa,  f.x, f.y);
                    mma16(ore[nb], npb, f.z, f.w);
                    mma16(oim[nb], pa,  f.z, f.w);
                    mma16(oim[nb], pb,  f.x, f.y);
                }
            }
        }

        __syncthreads();   // all smem tile reads done; reuse as output stage

        l0 += __shfl_xor_sync(~0u, l0, 1); l0 += __shfl_xor_sync(~0u, l0, 2);
        l1 += __shfl_xor_sync(~0u, l1, 1); l1 += __shfl_xor_sync(~0u, l1, 2);
        const float il0 = 1.0f / l0, il1 = 1.0f / l1;

        float* stg = (float*)sm;            // [64][132]: 0..63 re, 64..127 im
        #pragma unroll
        for (int nb = 0; nb < 8; ++nb) {
            const int d0 = nb * 8 + 2 * j4;
            stg[ r0      * 132 + d0    ]      = ore[nb][0] * il0;
            stg[ r0      * 132 + d0 + 1]      = ore[nb][1] * il0;
            stg[(r0 + 8) * 132 + d0    ]      = ore[nb][2] * il1;
            stg[(r0 + 8) * 132 + d0 + 1]      = ore[nb][3] * il1;
            stg[ r0      * 132 + 64 + d0]     = oim[nb][0] * il0;
            stg[ r0      * 132 + 64 + d0 + 1] = oim[nb][1] * il0;
            stg[(r0 + 8) * 132 + 64 + d0]     = oim[nb][2] * il1;
            stg[(r0 + 8) * 132 + 64 + d0 + 1] = oim[nb][3] * il1;
        }
        __syncthreads();

        for (int i = tid; i < QT * 32; i += THREADS) {
            const int row = i >> 5, c = i & 31;
            float4 v = *(const float4*)(stg + row * 132 + c * 4);
            if (c < 16)
                *(float4*)(out + bbH + (long long)(s0t + row) * DH + c * 4) = v;
            else
                *(float4*)(out + plane + bbH + (long long)(s0t + row) * DH + (c - 16) * 4) = v;
        }
        __syncthreads();   // stage consumed before next item's tile copies land
    }
}

extern "C" void kernel_launch(void* const* d_in, const int* in_sizes, int n_in,
                              void* d_out, int out_size) {
    const float* qr = (const float*)d_in[0];
    const float* qi = (const float*)d_in[1];
    const float* kr = (const float*)d_in[2];
    const float* ki = (const float*)d_in[3];
    const float* vr = (const float*)d_in[4];
    const float* vi = (const float*)d_in[5];

    const long long plane = (long long)in_sizes[0];   // B*H*S*D

    static int configured = 0;
    if (!configured) {
        cudaFuncSetAttribute(cv_attn_h9_kernel,
                             cudaFuncAttributeMaxDynamicSharedMemorySize, SMEM_BYTES);
        configured = 1;
    }

    prep_kernel<<<dim3(64, 2, 32), dim3(32, 8)>>>(qr, qi, kr, ki, vr, vi);
    cv_attn_h9_kernel<<<GRID, THREADS, SMEM_BYTES>>>((float*)d_out, plane);
}

// round 16
// speedup vs baseline: 1.1447x; 1.0518x over previous
#include <cuda_runtime.h>
#include <cuda_fp16.h>
#include <cstdint>

// Complex attention, fp16 m16n8k16 mma.sync. R13 main kernel VERBATIM (best
// measured: padded ROWB=176, 2-stage cp.async, fused p-pipeline, 2 CTAs/SM
// @255 regs) + single fused prep launch (ticket reset + Q/K->fp16 + V
// transpose) from R15.

#define S_LEN   2048
#define DH      64
#define BH      32
#define QT      64
#define NT      64
#define NTILES  (S_LEN / NT)
#define THREADS 128
#define NITEMS  1024            // 32 q-tiles x 32 heads
#define GRID    304             // 2 CTAs per SM
#define ROWB    176
#define PL_STR  (NT * ROWB)     // 11264

#define KP(buf, pl) (((buf) * 2 + (pl)) * PL_STR)
#define V_B     (4 * PL_STR)
#define VP(buf, pl) (V_B + ((buf) * 2 + (pl)) * PL_STR)
#define SMEM_BYTES (8 * PL_STR) // 90112

#define ELEMS (BH * S_LEN * DH)

__device__ __align__(16) __half gQr[ELEMS];
__device__ __align__(16) __half gQi[ELEMS];
__device__ __align__(16) __half gKr[ELEMS];
__device__ __align__(16) __half gKi[ELEMS];
__device__ __align__(16) __half gVtr[ELEMS];   // [bh][d][s]
__device__ __align__(16) __half gVti[ELEMS];

__device__ unsigned int g_ticket;

// ---- fused prep: ticket reset + Q/K fp32->fp16 (Q x 1/8) + V transpose ----
// grid (64, 2, 32), block (32, 8)
__global__ void prep_kernel(const float* __restrict__ q_r, const float* __restrict__ q_i,
                            const float* __restrict__ k_r, const float* __restrict__ k_i,
                            const float* __restrict__ v_r, const float* __restrict__ v_i)
{
    const int tx = threadIdx.x, ty = threadIdx.y;
    const int b  = blockIdx.x + 64 * (blockIdx.y + 2 * blockIdx.z);
    if (b == 0 && tx == 0 && ty == 0) g_ticket = 0u;

    // conv part: 4096 blocks x 1024 float4 = 4 tensors x 1048576 float4
    {
        const int t = ty * 32 + tx;
        #pragma unroll
        for (int i = 0; i < 4; ++i) {
            const int idx = b * 1024 + t + i * 256;
            const int ts  = idx >> 20;
            const int off = idx & 0xFFFFF;
            const float4* src = (ts == 0) ? (const float4*)q_r :
                                (ts == 1) ? (const float4*)q_i :
                                (ts == 2) ? (const float4*)k_r : (const float4*)k_i;
            __half* dst = (ts == 0) ? gQr : (ts == 1) ? gQi : (ts == 2) ? gKr : gKi;
            const float sc = (ts < 2) ? 0.125f : 1.0f;
            float4 v = src[off];
            __half2* d2 = (__half2*)(dst + (size_t)off * 4);
            d2[0] = __floats2half2_rn(v.x * sc, v.y * sc);
            d2[1] = __floats2half2_rn(v.z * sc, v.w * sc);
        }
    }

    // vt part: 32x32 tiled transpose
    __shared__ float tr[32][33], ti[32][33];
    const int s0 = blockIdx.x * 32, d0 = blockIdx.y * 32, bh = blockIdx.z;
    const long long ib = (long long)bh * S_LEN * DH;
    #pragma unroll
    for (int k = 0; k < 4; ++k) {
        int r = ty + k * 8;
        tr[r][tx] = v_r[ib + (long long)(s0 + r) * DH + d0 + tx];
        ti[r][tx] = v_i[ib + (long long)(s0 + r) * DH + d0 + tx];
    }
    __syncthreads();
    const long long ob = (long long)bh * DH * S_LEN;
    #pragma unroll
    for (int k = 0; k < 4; ++k) {
        int r = ty + k * 8;
        gVtr[ob + (long long)(d0 + r) * S_LEN + s0 + tx] = __float2half_rn(tr[tx][r]);
        gVti[ob + (long long)(d0 + r) * S_LEN + s0 + tx] = __float2half_rn(ti[tx][r]);
    }
}

// ---- helpers ----
__device__ __forceinline__ uint32_t cvta_s(const void* p) {
    uint32_t a;
    asm("{ .reg .u64 t; cvta.to.shared.u64 t, %1; cvt.u32.u64 %0, t; }" : "=r"(a) : "l"(p));
    return a;
}
__device__ __forceinline__ void cpa16(uint32_t dst, const void* src) {
    asm volatile("cp.async.ca.shared.global [%0], [%1], 16;" :: "r"(dst), "l"(src));
}
#define CP_COMMIT() asm volatile("cp.async.commit_group;" ::: "memory")
#define CP_WAIT0()  asm volatile("cp.async.wait_group 0;" ::: "memory")

__device__ __forceinline__ uint32_t pkh(float lo, float hi) {
    uint32_t d; asm("cvt.rn.f16x2.f32 %0, %1, %2;" : "=r"(d) : "f"(hi), "f"(lo)); return d;
}
__device__ __forceinline__ uint4 ldsm4(uint32_t a) {
    uint4 r;
    asm volatile("ldmatrix.sync.aligned.m8n8.x4.shared.b16 {%0,%1,%2,%3}, [%4];"
        : "=r"(r.x), "=r"(r.y), "=r"(r.z), "=r"(r.w) : "r"(a));
    return r;
}
__device__ __forceinline__ void mma16(float* d, const uint32_t* a, uint32_t b0, uint32_t b1) {
    asm volatile(
        "mma.sync.aligned.m16n8k16.row.col.f32.f16.f16.f32 "
        "{%0,%1,%2,%3}, {%4,%5,%6,%7}, {%8,%9}, {%0,%1,%2,%3};"
        : "+f"(d[0]), "+f"(d[1]), "+f"(d[2]), "+f"(d[3])
        : "r"(a[0]), "r"(a[1]), "r"(a[2]), "r"(a[3]), "r"(b0), "r"(b1));
}

__global__ __launch_bounds__(THREADS, 2)
void cv_attn_h10_kernel(float* __restrict__ out, long long plane)
{
    extern __shared__ char sm[];
    __shared__ int s_item;
    const uint32_t smb = cvta_s(sm);

    const int tid  = threadIdx.x;
    const int w    = tid >> 5;
    const int lane = tid & 31;
    const int g4   = lane >> 2;
    const int j4   = lane & 3;
    const int r0   = w * 16 + g4;      // rows 0..63

    const uint32_t laneLM = (uint32_t)((lane & 7) * ROWB)
                          + ((lane & 8) ? 16u : 0u)
                          + ((lane & 16) ? (uint32_t)PL_STR : 0u);

    for (;;) {
        if (tid == 0) s_item = (int)atomicAdd(&g_ticket, 1u);
        __syncthreads();
        const int item = s_item;
        if (item >= NITEMS) break;

        const int bh  = item >> 5;
        const int s0t = (item & 31) * QT;
        const long long bbH = (long long)bh * S_LEN * DH;

        auto copy_tile = [&](int t, int buf) {
            #pragma unroll
            for (int it = 0; it < 16; ++it) {
                const int i = tid + it * THREADS;    // 2048 x 16B chunks
                const int tensor = i >> 10;          // 0:K 1:Vt
                const int pl  = (i >> 9) & 1;
                const int row = (i >> 3) & 63;
                const int c16 = i & 7;
                const __half* src;
                uint32_t dst;
                if (tensor == 0) {
                    src = (pl ? gKi : gKr) + bbH + (long long)(t * NT + row) * DH + c16 * 8;
                    dst = smb + (uint32_t)KP(buf, pl) + (uint32_t)(row * ROWB + c16 * 16);
                } else {
                    src = (pl ? gVti : gVtr) + bbH + (long long)row * S_LEN + t * NT + c16 * 8;
                    dst = smb + (uint32_t)VP(buf, pl) + (uint32_t)(row * ROWB + c16 * 16);
                }
                cpa16(dst, src);
            }
            CP_COMMIT();
        };

        // ---- Q fragments -> registers (fp16 gmem, already scaled); nqb hoisted ----
        uint32_t qfr[4][4], qfi[4][4], nqb[4][4];
        {
            const long long b0 = bbH + (long long)(s0t + r0) * DH;
            const long long b8 = bbH + (long long)(s0t + r0 + 8) * DH;
            #pragma unroll
            for (int ks = 0; ks < 4; ++ks) {
                const int c = ks * 16 + 2 * j4;
                qfr[ks][0] = *(const uint32_t*)(gQr + b0 + c);
                qfr[ks][1] = *(const uint32_t*)(gQr + b8 + c);
                qfr[ks][2] = *(const uint32_t*)(gQr + b0 + c + 8);
                qfr[ks][3] = *(const uint32_t*)(gQr + b8 + c + 8);
                qfi[ks][0] = *(const uint32_t*)(gQi + b0 + c);
                qfi[ks][1] = *(const uint32_t*)(gQi + b8 + c);
                qfi[ks][2] = *(const uint32_t*)(gQi + b0 + c + 8);
                qfi[ks][3] = *(const uint32_t*)(gQi + b8 + c + 8);
                #pragma unroll
                for (int k = 0; k < 4; ++k) nqb[ks][k] = qfi[ks][k] ^ 0x80008000u;
            }
        }

        copy_tile(0, 0);

        float ore[8][4], oim[8][4];
        #pragma unroll
        for (int nb = 0; nb < 8; ++nb)
            #pragma unroll
            for (int c = 0; c < 4; ++c) { ore[nb][c] = 0.f; oim[nb][c] = 0.f; }
        float l0 = 0.f, l1 = 0.f;

        for (int t = 0; t < NTILES; ++t) {
            const int cur = t & 1;
            CP_WAIT0();
            __syncthreads();
            if (t + 1 < NTILES) copy_tile(t + 1, cur ^ 1);

            const uint32_t kbase = smb + (uint32_t)KP(cur, 0) + laneLM;
            const uint32_t vbase = smb + (uint32_t)VP(cur, 0) + laneLM;

            // ---- fused pipeline over nb-pairs p: GEMM1 -> epilogue -> GEMM2(ks=p) ----
            #pragma unroll
            for (int p = 0; p < 4; ++p) {
                float sre[2][4], sim[2][4];
                #pragma unroll
                for (int b = 0; b < 2; ++b)
                    #pragma unroll
                    for (int c = 0; c < 4; ++c) { sre[b][c] = 0.f; sim[b][c] = 0.f; }

                #pragma unroll
                for (int ks = 0; ks < 4; ++ks) {
                    #pragma unroll
                    for (int b = 0; b < 2; ++b) {
                        uint4 f = ldsm4(kbase + (2 * p + b) * (8 * ROWB) + ks * 32);
                        mma16(sre[b], qfr[ks], f.x, f.y);
                        mma16(sre[b], nqb[ks], f.z, f.w);
                        mma16(sim[b], qfr[ks], f.z, f.w);
                        mma16(sim[b], qfi[ks], f.x, f.y);
                    }
                }

                #pragma unroll
                for (int b = 0; b < 2; ++b) {
                    #pragma unroll
                    for (int c = 0; c < 4; ++c) {
                        float re = sre[b][c], im = sim[b][c];
                        float m2  = fmaxf(fmaf(re, re, im * im), 1e-24f);
                        float inv = rsqrtf(m2);
                        float mag = m2 * inv;
                        float e   = __expf(mag);
                        if (c < 2) l0 += e; else l1 += e;
                        float pw = e * inv;
                        sre[b][c] = re * pw;
                        sim[b][c] = im * pw;
                    }
                }

                uint32_t pa[4], pb[4], npb[4];
                pa[0] = pkh(sre[0][0], sre[0][1]);
                pa[1] = pkh(sre[0][2], sre[0][3]);
                pa[2] = pkh(sre[1][0], sre[1][1]);
                pa[3] = pkh(sre[1][2], sre[1][3]);
                pb[0] = pkh(sim[0][0], sim[0][1]);
                pb[1] = pkh(sim[0][2], sim[0][3]);
                pb[2] = pkh(sim[1][0], sim[1][1]);
                pb[3] = pkh(sim[1][2], sim[1][3]);
                #pragma unroll
                for (int k = 0; k < 4; ++k) npb[k] = pb[k] ^ 0x80008000u;

                // GEMM2 slice ks = p
                #pragma unroll
                for (int nb = 0; nb < 8; ++nb) {
                    uint4 f = ldsm4(vbase + nb * (8 * ROWB) + p * 32);
                    mma16(ore[nb], pa,  f.x, f.y);
                    mma16(ore[nb], npb, f.z, f.w);
                    mma16(oim[nb], pa,  f.z, f.w);
                    mma16(oim[nb], pb,  f.x, f.y);
                }
            }
        }

        __syncthreads();   // all smem tile reads done; reuse as output stage

        l0 += __shfl_xor_sync(~0u, l0, 1); l0 += __shfl_xor_sync(~0u, l0, 2);
        l1 += __shfl_xor_sync(~0u, l1, 1); l1 += __shfl_xor_sync(~0u, l1, 2);
        const float il0 = 1.0f / l0, il1 = 1.0f / l1;

        float* stg = (float*)sm;            // [64][132]: 0..63 re, 64..127 im
        #pragma unroll
        for (int nb = 0; nb < 8; ++nb) {
            const int d0 = nb * 8 + 2 * j4;
            stg[ r0      * 132 + d0    ]      = ore[nb][0] * il0;
            stg[ r0      * 132 + d0 + 1]      = ore[nb][1] * il0;
            stg[(r0 + 8) * 132 + d0    ]      = ore[nb][2] * il1;
            stg[(r0 + 8) * 132 + d0 + 1]      = ore[nb][3] * il1;
            stg[ r0      * 132 + 64 + d0]     = oim[nb][0] * il0;
            stg[ r0      * 132 + 64 + d0 + 1] = oim[nb][1] * il0;
            stg[(r0 + 8) * 132 + 64 + d0]     = oim[nb][2] * il1;
            stg[(r0 + 8) * 132 + 64 + d0 + 1] = oim[nb][3] * il1;
        }
        __syncthreads();

        for (int i = tid; i < QT * 32; i += THREADS) {
            const int row = i >> 5, c = i & 31;
            float4 v = *(const float4*)(stg + row * 132 + c * 4);
            if (c < 16)
                *(float4*)(out + bbH + (long long)(s0t + row) * DH + c * 4) = v;
            else
                *(float4*)(out + plane + bbH + (long long)(s0t + row) * DH + (c - 16) * 4) = v;
        }
        __syncthreads();   // stage consumed before next item's tile copies land
    }
}

extern "C" void kernel_launch(void* const* d_in, const int* in_sizes, int n_in,
                              void* d_out, int out_size) {
    const float* qr = (const float*)d_in[0];
    const float* qi = (const float*)d_in[1];
    const float* kr = (const float*)d_in[2];
    const float* ki = (const float*)d_in[3];
    const float* vr = (const float*)d_in[4];
    const float* vi = (const float*)d_in[5];

    const long long plane = (long long)in_sizes[0];   // B*H*S*D

    static int configured = 0;
    if (!configured) {
        cudaFuncSetAttribute(cv_attn_h10_kernel,
                             cudaFuncAttributeMaxDynamicSharedMemorySize, SMEM_BYTES);
        configured = 1;
    }

    prep_kernel<<<dim3(64, 2, 32), dim3(32, 8)>>>(qr, qi, kr, ki, vr, vi);
    cv_attn_h10_kernel<<<GRID, THREADS, SMEM_BYTES>>>((float*)d_out, plane);
}